// round 9
// baseline (speedup 1.0000x reference)
#include <cuda_runtime.h>
#include <cuda_fp16.h>
#include <mma.h>

using namespace nvcuda;

#define N_NODES 100000
#define N_EDGES 3200000
#define CH      128
#define NG      256
#define NC      32
#define APAD    136   // half elements per smem row (128 + 8)

// ---------------- scratch ----------------
__device__ unsigned char g_y8[(size_t)N_NODES * CH]; // quantized (x@W)*dinv rows (12.8 MB)
__device__ float  g_yscale[N_NODES];                 // per-node dequant scale
__device__ __half g_h[(size_t)N_NODES * CH];         // layer output, fp16
__device__ float  g_dinv[N_NODES];
__device__ int    g_deg[N_NODES];
__device__ int    g_rowptr[N_NODES + 1];
__device__ int    g_cursor[N_NODES];
__device__ int    g_csrc[N_EDGES];
__device__ float  g_pool[NG * CH];

// ---------------- CSR construction ----------------
__global__ void init_deg_k() {
    int v = blockIdx.x * blockDim.x + threadIdx.x;
    if (v < N_NODES) g_deg[v] = 1;   // self-loop
}

__global__ void hist_k(const int4* __restrict__ dst4) {
    int stride = gridDim.x * blockDim.x;
    int i = blockIdx.x * blockDim.x + threadIdx.x;
    for (; i + stride < N_EDGES / 4; i += 2 * stride) {
        int4 d0 = dst4[i];
        int4 d1 = dst4[i + stride];
        atomicAdd(&g_deg[d0.x], 1);
        atomicAdd(&g_deg[d0.y], 1);
        atomicAdd(&g_deg[d0.z], 1);
        atomicAdd(&g_deg[d0.w], 1);
        atomicAdd(&g_deg[d1.x], 1);
        atomicAdd(&g_deg[d1.y], 1);
        atomicAdd(&g_deg[d1.z], 1);
        atomicAdd(&g_deg[d1.w], 1);
    }
    if (i < N_EDGES / 4) {
        int4 d = dst4[i];
        atomicAdd(&g_deg[d.x], 1);
        atomicAdd(&g_deg[d.y], 1);
        atomicAdd(&g_deg[d.z], 1);
        atomicAdd(&g_deg[d.w], 1);
    }
}

__global__ void scan_k() {
    __shared__ int ssum[1024];
    const int CHUNK = (N_NODES + 1023) / 1024;
    int t  = threadIdx.x;
    int lo = t * CHUNK;
    int hi = min(lo + CHUNK, N_NODES);
    int s = 0;
    for (int v = lo; v < hi; v++) s += g_deg[v] - 1;
    ssum[t] = s;
    __syncthreads();
    for (int off = 1; off < 1024; off <<= 1) {
        int val = (t >= off) ? ssum[t - off] : 0;
        __syncthreads();
        ssum[t] += val;
        __syncthreads();
    }
    int run = (t == 0) ? 0 : ssum[t - 1];
    for (int v = lo; v < hi; v++) {
        g_rowptr[v] = run;
        g_cursor[v] = run;
        int d = g_deg[v];
        run += d - 1;
        g_dinv[v] = rsqrtf((float)d);
    }
    if (t == 1023) g_rowptr[N_NODES] = N_EDGES;
}

__global__ void fill_k(const int4* __restrict__ src4, const int4* __restrict__ dst4) {
    int stride = gridDim.x * blockDim.x;
    int i = blockIdx.x * blockDim.x + threadIdx.x;
    for (; i + stride < N_EDGES / 4; i += 2 * stride) {
        int4 s0 = src4[i];
        int4 d0 = dst4[i];
        int4 s1 = src4[i + stride];
        int4 d1 = dst4[i + stride];
        int p0 = atomicAdd(&g_cursor[d0.x], 1);
        int p1 = atomicAdd(&g_cursor[d0.y], 1);
        int p2 = atomicAdd(&g_cursor[d0.z], 1);
        int p3 = atomicAdd(&g_cursor[d0.w], 1);
        int p4 = atomicAdd(&g_cursor[d1.x], 1);
        int p5 = atomicAdd(&g_cursor[d1.y], 1);
        int p6 = atomicAdd(&g_cursor[d1.z], 1);
        int p7 = atomicAdd(&g_cursor[d1.w], 1);
        g_csrc[p0] = s0.x;
        g_csrc[p1] = s0.y;
        g_csrc[p2] = s0.z;
        g_csrc[p3] = s0.w;
        g_csrc[p4] = s1.x;
        g_csrc[p5] = s1.y;
        g_csrc[p6] = s1.z;
        g_csrc[p7] = s1.w;
    }
    if (i < N_EDGES / 4) {
        int4 s = src4[i];
        int4 d = dst4[i];
        int p0 = atomicAdd(&g_cursor[d.x], 1);
        int p1 = atomicAdd(&g_cursor[d.y], 1);
        int p2 = atomicAdd(&g_cursor[d.z], 1);
        int p3 = atomicAdd(&g_cursor[d.w], 1);
        g_csrc[p0] = s.x;
        g_csrc[p1] = s.y;
        g_csrc[p2] = s.z;
        g_csrc[p3] = s.w;
    }
}

// ---------------- GEMM (tensor core) + int8 quantize epilogue ----------------
// g_y8[row] = int8 round((A@W)[row] * dinv[row] / scale_row), g_yscale[row] = scale_row
#define GEMM_SMEM (2 * 128 * APAD * 2)

template <int A_IS_HALF>
__global__ void __launch_bounds__(256) gemm_wmma_k(
    const float* __restrict__ Af, const float* __restrict__ W, int M)
{
    extern __shared__ char smraw[];
    __half* As = (__half*)smraw;                         // [128][APAD]
    __half* Bs = (__half*)(smraw + 128 * APAD * 2);      // [128][APAD], B[k][n]
    float*  Cs = (float*)smraw;                          // [128][128] staging (reused)

    int tid = threadIdx.x;

    // W -> Bs straight copy+convert
    for (int i = tid; i < 128 * 32; i += 256) {
        int k = i >> 5, c4 = i & 31;
        float4 v = *(const float4*)&W[k * 128 + c4 * 4];
        __half2 h0 = __floats2half2_rn(v.x, v.y);
        __half2 h1 = __floats2half2_rn(v.z, v.w);
        *(uint2*)&Bs[k * APAD + c4 * 4] = make_uint2(*(unsigned*)&h0, *(unsigned*)&h1);
    }

    int row0 = blockIdx.x * 128;
    if (A_IS_HALF) {
        const __half* Ah = g_h;
        for (int i = tid; i < 128 * 16; i += 256) {
            int r = i >> 4, c8 = i & 15;
            uint4 v = make_uint4(0u, 0u, 0u, 0u);
            if (row0 + r < M) v = *(const uint4*)&Ah[(size_t)(row0 + r) * CH + c8 * 8];
            *(uint4*)&As[r * APAD + c8 * 8] = v;
        }
    } else {
        for (int i = tid; i < 128 * 32; i += 256) {
            int r = i >> 5, c4 = i & 31;
            float4 v = make_float4(0.f, 0.f, 0.f, 0.f);
            if (row0 + r < M) v = *(const float4*)&Af[(size_t)(row0 + r) * CH + c4 * 4];
            __half2 h0 = __floats2half2_rn(v.x, v.y);
            __half2 h1 = __floats2half2_rn(v.z, v.w);
            *(uint2*)&As[r * APAD + c4 * 4] = make_uint2(*(unsigned*)&h0, *(unsigned*)&h1);
        }
    }
    __syncthreads();

    int wid = tid >> 5;
    int wm = wid >> 2, wn = wid & 3;
    int wrow = wm * 64, wcol = wn * 32;

    wmma::fragment<wmma::accumulator, 16, 16, 16, float> c[4][2];
    #pragma unroll
    for (int i = 0; i < 4; i++)
        #pragma unroll
        for (int j = 0; j < 2; j++) wmma::fill_fragment(c[i][j], 0.f);

    #pragma unroll
    for (int kk = 0; kk < 128; kk += 16) {
        wmma::fragment<wmma::matrix_a, 16, 16, 16, __half, wmma::row_major> a[4];
        wmma::fragment<wmma::matrix_b, 16, 16, 16, __half, wmma::row_major> b[2];
        #pragma unroll
        for (int i = 0; i < 4; i++)
            wmma::load_matrix_sync(a[i], As + (wrow + i * 16) * APAD + kk, APAD);
        #pragma unroll
        for (int j = 0; j < 2; j++)
            wmma::load_matrix_sync(b[j], Bs + kk * APAD + wcol + j * 16, APAD);
        #pragma unroll
        for (int i = 0; i < 4; i++)
            #pragma unroll
            for (int j = 0; j < 2; j++)
                wmma::mma_sync(c[i][j], a[i], b[j], c[i][j]);
    }

    __syncthreads();
    #pragma unroll
    for (int i = 0; i < 4; i++)
        #pragma unroll
        for (int j = 0; j < 2; j++)
            wmma::store_matrix_sync(Cs + (wrow + i * 16) * 128 + wcol + j * 16,
                                    c[i][j], 128, wmma::mem_row_major);
    __syncthreads();

    // epilogue: per-row absmax (16-lane shfl reduce), quantize to int8, store scale
    for (int i = tid; i < 128 * 16; i += 256) {
        int r = i >> 4, c8 = i & 15;
        int gr = row0 + r;
        float dv = (gr < M) ? g_dinv[gr] : 0.f;
        const float* s = &Cs[r * 128 + c8 * 8];
        float v[8];
        #pragma unroll
        for (int j = 0; j < 8; j++) v[j] = s[j] * dv;
        float amax = 0.f;
        #pragma unroll
        for (int j = 0; j < 8; j++) amax = fmaxf(amax, fabsf(v[j]));
        #pragma unroll
        for (int off = 1; off < 16; off <<= 1)
            amax = fmaxf(amax, __shfl_xor_sync(0xffffffffu, amax, off));
        float inv = amax > 0.f ? __fdividef(127.f, amax) : 0.f;
        int q[8];
        #pragma unroll
        for (int j = 0; j < 8; j++) q[j] = __float2int_rn(v[j] * inv);
        unsigned u0 = (q[0] & 0xff) | ((q[1] & 0xff) << 8) |
                      ((q[2] & 0xff) << 16) | (q[3] << 24);
        unsigned u1 = (q[4] & 0xff) | ((q[5] & 0xff) << 8) |
                      ((q[6] & 0xff) << 16) | (q[7] << 24);
        if (gr < M) {
            *(uint2*)&g_y8[(size_t)gr * CH + c8 * 8] = make_uint2(u0, u1);
            if (c8 == 0) g_yscale[gr] = amax * (1.f / 127.f);
        }
    }
}

// ---------------- aggregation: warp/node, int8 payload, per-node scale ----------------
__device__ __forceinline__ void accq(float* a, unsigned u, float sc) {
    int b0 = (int)(signed char)(u);
    int b1 = (int)(signed char)(u >> 8);
    int b2 = (int)(signed char)(u >> 16);
    int b3 = ((int)u) >> 24;
    a[0] = fmaf((float)b0, sc, a[0]);
    a[1] = fmaf((float)b1, sc, a[1]);
    a[2] = fmaf((float)b2, sc, a[2]);
    a[3] = fmaf((float)b3, sc, a[3]);
}

__global__ void __launch_bounds__(256) aggregate_k(const float* __restrict__ bias) {
    int w = (blockIdx.x * blockDim.x + threadIdx.x) >> 5;
    if (w >= N_NODES) return;
    int lane = threadIdx.x & 31;

    const unsigned* y1 = (const unsigned*)g_y8;   // row = 32 uints (128 int8)

    float acc[4] = {0.f, 0.f, 0.f, 0.f};
    accq(acc, y1[(size_t)w * 32 + lane], g_yscale[w]);   // self-loop

    int beg = g_rowptr[w], end = g_rowptr[w + 1];
    int i = beg;
    for (; i + 32 <= end; i += 32) {
        int idx = g_csrc[i + lane];
        float sc = g_yscale[idx];
        #pragma unroll
        for (int j = 0; j < 32; j++) {
            int   s   = __shfl_sync(0xffffffffu, idx, j);
            float scj = __shfl_sync(0xffffffffu, sc,  j);
            accq(acc, y1[(size_t)s * 32 + lane], scj);
        }
    }
    if (i < end) {
        int cnt = end - i;
        int cl  = min(i + lane, end - 1);
        int idx = g_csrc[cl];
        float sc = g_yscale[idx];
        for (int j = 0; j < cnt; j++) {
            int   s   = __shfl_sync(0xffffffffu, idx, j);
            float scj = __shfl_sync(0xffffffffu, sc,  j);
            accq(acc, y1[(size_t)s * 32 + lane], scj);
        }
    }

    float dv = g_dinv[w];
    float4 b = ((const float4*)bias)[lane];
    float r0 = fmaxf(fmaf(acc[0], dv, b.x), 0.f);
    float r1 = fmaxf(fmaf(acc[1], dv, b.y), 0.f);
    float r2 = fmaxf(fmaf(acc[2], dv, b.z), 0.f);
    float r3 = fmaxf(fmaf(acc[3], dv, b.w), 0.f);
    __half2 h0 = __floats2half2_rn(r0, r1);
    __half2 h1 = __floats2half2_rn(r2, r3);
    ((uint2*)g_h)[(size_t)w * 32 + lane] =
        make_uint2(*(unsigned*)&h0, *(unsigned*)&h1);
}

// ---------------- pooling + FC ----------------
__device__ __forceinline__ int lower_bound_i(const int* a, int n, int key) {
    int lo = 0, hi = n;
    while (lo < hi) { int mid = (lo + hi) >> 1; if (a[mid] < key) lo = mid + 1; else hi = mid; }
    return lo;
}

__global__ void pool_k(const int* __restrict__ batch) {
    int g = blockIdx.x;
    __shared__ int slo, shi;
    if (threadIdx.x == 0) {
        slo = lower_bound_i(batch, N_NODES, g);
        shi = lower_bound_i(batch, N_NODES, g + 1);
    }
    __syncthreads();
    int lo = slo, hi = shi;
    int c = threadIdx.x;
    float s = 0.f;
    for (int r = lo; r < hi; r++) s += __half2float(g_h[(size_t)r * CH + c]);
    float cnt = (float)(hi - lo);
    g_pool[g * CH + c] = s / fmaxf(cnt, 1.0f);
}

__global__ void fc_k(const float* __restrict__ Wfc, const float* __restrict__ bfc,
                     float* __restrict__ out) {
    int g = blockIdx.x;
    int c = threadIdx.x;
    float acc = bfc[c];
    #pragma unroll 4
    for (int k = 0; k < CH; k++)
        acc = fmaf(g_pool[g * CH + k], Wfc[k * NC + c], acc);
    out[g * NC + c] = acc;
}

// ---------------- launcher ----------------
extern "C" void kernel_launch(void* const* d_in, const int* in_sizes, int n_in,
                              void* d_out, int out_size) {
    const float* x     = (const float*)d_in[0];
    const int*   ei    = (const int*)  d_in[1];
    const int*   batch = (const int*)  d_in[2];
    const float* W1    = (const float*)d_in[3];
    const float* b1    = (const float*)d_in[4];
    const float* W2    = (const float*)d_in[5];
    const float* b2    = (const float*)d_in[6];
    const float* Wfc   = (const float*)d_in[7];
    const float* bfc   = (const float*)d_in[8];
    float* out = (float*)d_out;

    const int4* src4 = (const int4*)ei;
    const int4* dst4 = (const int4*)(ei + N_EDGES);

    static cudaStream_t s2 = nullptr;
    static cudaEvent_t  e0 = nullptr, e1 = nullptr;
    if (!s2) {
        cudaStreamCreate(&s2);
        cudaEventCreateWithFlags(&e0, cudaEventDisableTiming);
        cudaEventCreateWithFlags(&e1, cudaEventDisableTiming);
        cudaFuncSetAttribute(gemm_wmma_k<0>,
                             cudaFuncAttributeMaxDynamicSharedMemorySize, GEMM_SMEM);
        cudaFuncSetAttribute(gemm_wmma_k<1>,
                             cudaFuncAttributeMaxDynamicSharedMemorySize, GEMM_SMEM);
    }

    int gemm_blocks = (N_NODES + 127) / 128;
    int agg_blocks  = (N_NODES * 32 + 255) / 256;

    // serial prefix: deg + scan
    init_deg_k<<<(N_NODES + 255) / 256, 256>>>();
    hist_k<<<1184, 256>>>(dst4);
    scan_k<<<1, 1024>>>();

    // fork: fill_k on s2 concurrent with gemm1
    cudaEventRecord(e0, 0);
    cudaStreamWaitEvent(s2, e0, 0);
    fill_k<<<1184, 256, 0, s2>>>(src4, dst4);
    gemm_wmma_k<0><<<gemm_blocks, 256, GEMM_SMEM>>>(x, W1, N_NODES);
    cudaEventRecord(e1, s2);
    cudaStreamWaitEvent(0, e1, 0);

    // layer 1
    aggregate_k<<<agg_blocks, 256>>>(b1);
    // layer 2
    gemm_wmma_k<1><<<gemm_blocks, 256, GEMM_SMEM>>>(nullptr, W2, N_NODES);
    aggregate_k<<<agg_blocks, 256>>>(b2);
    // pool + fc
    pool_k<<<NG, 128>>>(batch);
    fc_k<<<NG, NC>>>(Wfc, bfc, out);
}